// round 15
// baseline (speedup 1.0000x reference)
#include <cuda_runtime.h>
#include <cuda_fp16.h>
#include <cuda_bf16.h>
#include <cstdint>
#include <cstddef>

#define MDIM 8192
#define KDIM 4096
#define NDIM 4096
#define NBLK 32            // K blocks of 128 for weight scales

// ---------------- static device scratch ----------------
__device__ __align__(1024) signed char g_xq[(size_t)MDIM * KDIM];  // int8 activations
__device__ __align__(1024) signed char g_wq[(size_t)NDIM * KDIM];  // int8 weights (packed from int32 input)
__device__ float g_xs[MDIM];                                        // per-row activation scales

// ---------------- helpers ----------------
__device__ __forceinline__ uint32_t smem_u32(const void* p) {
    uint32_t a;
    asm("{ .reg .u64 t; cvta.to.shared.u64 t, %1; cvt.u32.u64 %0, t; }" : "=r"(a) : "l"(p));
    return a;
}
__device__ __forceinline__ void cp_async16(uint32_t dst_smem, const void* src) {
    asm volatile("cp.async.cg.shared.global [%0], [%1], 16;" :: "r"(dst_smem), "l"(src) : "memory");
}
__device__ __forceinline__ void cp_commit() {
    asm volatile("cp.async.commit_group;" ::: "memory");
}
__device__ __forceinline__ void ldsm_x4(uint32_t* r, uint32_t addr) {
    asm volatile("ldmatrix.sync.aligned.m8n8.x4.shared.b16 {%0,%1,%2,%3}, [%4];"
        : "=r"(r[0]), "=r"(r[1]), "=r"(r[2]), "=r"(r[3]) : "r"(addr));
}
__device__ __forceinline__ void imma16832(int* d, const uint32_t* a, uint32_t b0, uint32_t b1) {
    asm volatile("mma.sync.aligned.m16n8k32.row.col.s32.s8.s8.s32 "
        "{%0,%1,%2,%3}, {%4,%5,%6,%7}, {%8,%9}, {%0,%1,%2,%3};"
        : "+r"(d[0]), "+r"(d[1]), "+r"(d[2]), "+r"(d[3])
        : "r"(a[0]), "r"(a[1]), "r"(a[2]), "r"(a[3]), "r"(b0), "r"(b1));
}
__device__ __forceinline__ void stg_cs_f2(float* p, float2 v) {
    asm volatile("st.global.cs.v2.f32 [%0], {%1, %2};" :: "l"(p), "f"(v.x), "f"(v.y) : "memory");
}
__device__ __forceinline__ uint32_t pack4b(int a, int b, int c, int d) {
    return (uint32_t)(a & 0xFF) | ((uint32_t)(b & 0xFF) << 8) |
           ((uint32_t)(c & 0xFF) << 16) | ((uint32_t)(d & 0xFF) << 24);
}

// ---------------- kernel 1: fused prep (quant x rows | pack weight rows), 16B stores ----------------
__global__ void __launch_bounds__(256) prep_kernel(const float* __restrict__ x,
                                                   const int* __restrict__ wq32) {
    const int t = threadIdx.x;
    if (blockIdx.x >= MDIM) {
        // pack one weight row: 4 consecutive int4 in -> one int4 (16 bytes) out
        const int r = blockIdx.x - MDIM;
        const int4* src = reinterpret_cast<const int4*>(wq32 + (size_t)r * KDIM);
        uint4* dst = reinterpret_cast<uint4*>(g_wq + (size_t)r * KDIM);
        int4 v[4];
#pragma unroll
        for (int j = 0; j < 4; j++) v[j] = src[4 * t + j];
        uint4 o;
        o.x = pack4b(v[0].x, v[0].y, v[0].z, v[0].w);
        o.y = pack4b(v[1].x, v[1].y, v[1].z, v[1].w);
        o.z = pack4b(v[2].x, v[2].y, v[2].z, v[2].w);
        o.w = pack4b(v[3].x, v[3].y, v[3].z, v[3].w);
        dst[t] = o;
        return;
    }
    // quantize one activation row: 4 consecutive float4 in -> one int4 out
    const int row = blockIdx.x;
    const float4* xr = reinterpret_cast<const float4*>(x) + (size_t)row * (KDIM / 4);
    float4 v[4];
    float amax = 0.f;
#pragma unroll
    for (int j = 0; j < 4; j++) {
        v[j] = xr[4 * t + j];
        amax = fmaxf(amax, fmaxf(fmaxf(fabsf(v[j].x), fabsf(v[j].y)), fmaxf(fabsf(v[j].z), fabsf(v[j].w))));
    }
#pragma unroll
    for (int o = 16; o; o >>= 1) amax = fmaxf(amax, __shfl_xor_sync(0xffffffffu, amax, o));
    __shared__ float warpmax[8];
    __shared__ float s_scale;
    if ((t & 31) == 0) warpmax[t >> 5] = amax;
    __syncthreads();
    if (t == 0) {
        float m = warpmax[0];
#pragma unroll
        for (int i = 1; i < 8; i++) m = fmaxf(m, warpmax[i]);
        float s = fmaxf(m, 1e-6f) / 127.0f;
        g_xs[row] = s;
        s_scale = s;
    }
    __syncthreads();
    const float s = s_scale;
    uint4 o;
    uint32_t* op = &o.x;
#pragma unroll
    for (int j = 0; j < 4; j++) {
        int qa = max(-128, min(127, __float2int_rn(v[j].x / s)));
        int qb = max(-128, min(127, __float2int_rn(v[j].y / s)));
        int qc = max(-128, min(127, __float2int_rn(v[j].z / s)));
        int qd = max(-128, min(127, __float2int_rn(v[j].w / s)));
        op[j] = pack4b(qa, qb, qc, qd);
    }
    reinterpret_cast<uint4*>(g_xq + (size_t)row * KDIM)[t] = o;
}

// ---------------- kernel 2: int8 GEMM, CTA 64(M)x64(N), 256 thr, 3 CTAs/SM ----------------
// 8 warps: wm = wid&1 (M offset 32*wm), wn = wid>>1 (N offset 16*wn). Warp tile 32x16.
// One B ldmatrix.x4 per k32 step covers n16 x k32 (frags 0,1 = rows0-7; 2,3 = rows8-15).
// SMEM rows padded to 144B for conflict-free ldmatrix. Weight scales prefetched via __ldg.

#define ROWB 144
#define TILE_A_BYTES (64 * ROWB)           // 9216
#define TILE_B_BYTES (64 * ROWB)           // 9216
#define STAGE_BYTES (TILE_A_BYTES + TILE_B_BYTES)   // 18432
#define STAGES 4
#define SMEM_DYN (STAGES * STAGE_BYTES)    // 73728 -> 3 CTAs/SM (216KB)

__device__ __forceinline__ void load_stage(uint32_t sbase, const signed char* gA,
                                           const signed char* gB, int blk, int tid) {
    const int koff = blk * 128;
#pragma unroll
    for (int i = 0; i < 2; i++) {            // A: 512 x 16B chunks, 256 threads
        int idx = tid + i * 256;
        int r = idx >> 3, c = idx & 7;
        cp_async16(sbase + (uint32_t)r * ROWB + (uint32_t)(c << 4),
                   gA + (size_t)r * KDIM + koff + c * 16);
    }
    uint32_t bb = sbase + TILE_A_BYTES;
#pragma unroll
    for (int i = 0; i < 2; i++) {            // B: 512 x 16B chunks
        int idx = tid + i * 256;
        int r = idx >> 3, c = idx & 7;
        cp_async16(bb + (uint32_t)r * ROWB + (uint32_t)(c << 4),
                   gB + (size_t)r * KDIM + koff + c * 16);
    }
}

__global__ void __launch_bounds__(256, 3) gemm_kernel(const float* __restrict__ ws,
                                                      const float* __restrict__ bias,
                                                      float* __restrict__ out) {
    extern __shared__ char dsm[];

    const int tid = threadIdx.x;
    const int wid = tid >> 5;
    const int lane = tid & 31;
    const int wm = wid & 1;                  // M offset 32*wm
    const int wn = wid >> 1;                 // N offset 16*wn (0..3)
    const int m0 = blockIdx.y * 64;
    const int n0 = blockIdx.x * 64;
    const uint32_t sbase0 = smem_u32(dsm);

    const signed char* gA = g_xq + (size_t)m0 * KDIM;
    const signed char* gB = g_wq + (size_t)n0 * KDIM;

    float facc[2][2][4];
#pragma unroll
    for (int mt = 0; mt < 2; mt++)
#pragma unroll
        for (int nt = 0; nt < 2; nt++)
#pragma unroll
            for (int r = 0; r < 4; r++) facc[mt][nt][r] = 0.f;

    // prologue: fill 3 stages
#pragma unroll
    for (int s = 0; s < 3; s++) {
        load_stage(sbase0 + s * STAGE_BYTES, gA, gB, s, tid);
        cp_commit();
    }

    // ldmatrix base offsets (within a stage)
    const uint32_t a_lrow = (uint32_t)(wm * 32 + (lane & 15)) * ROWB + (uint32_t)(lane & 16);
    const uint32_t b_lrow = (uint32_t)(wn * 16 + (lane & 7) + ((lane & 16) >> 1)) * ROWB
                          + (uint32_t)((lane & 8) << 1);

    // per-thread weight-scale pointer: ws[blk*NDIM + col], col = n0 + wn*16 + nt*8 + (lane&3)*2
    const float* wsp = ws + n0 + wn * 16 + (lane & 3) * 2;

    for (int blk = 0; blk < NBLK; blk++) {
        // prefetch this block's scales early so L2 latency overlaps the MMA chain
        const float* wsb = wsp + (size_t)blk * NDIM;
        const float2 s2a = __ldg(reinterpret_cast<const float2*>(wsb));
        const float2 s2b = __ldg(reinterpret_cast<const float2*>(wsb + 8));

        asm volatile("cp.async.wait_group 2;" ::: "memory");
        __syncthreads();   // stage blk visible; all warps done with stage blk-1

        if (blk + 3 < NBLK)
            load_stage(sbase0 + ((blk + 3) & 3) * STAGE_BYTES, gA, gB, blk + 3, tid);
        cp_commit();

        const uint32_t abase = sbase0 + (blk & 3) * STAGE_BYTES;
        const uint32_t bbase = abase + TILE_A_BYTES;

        int ci[2][2][4];
#pragma unroll
        for (int mt = 0; mt < 2; mt++)
#pragma unroll
            for (int nt = 0; nt < 2; nt++)
#pragma unroll
                for (int r = 0; r < 4; r++) ci[mt][nt][r] = 0;

#pragma unroll
        for (int ks = 0; ks < 4; ks++) {
            const uint32_t kb = ks * 32;
            uint32_t af[2][4];
#pragma unroll
            for (int mt = 0; mt < 2; mt++)
                ldsm_x4(af[mt], abase + a_lrow + (uint32_t)(mt * 16) * ROWB + kb);
            uint32_t bf[4];
            ldsm_x4(bf, bbase + b_lrow + kb);
#pragma unroll
            for (int mt = 0; mt < 2; mt++)
#pragma unroll
                for (int nt = 0; nt < 2; nt++)
                    imma16832(ci[mt][nt], af[mt], bf[nt * 2], bf[nt * 2 + 1]);
        }

        // per-block fp32 fixup with prefetched scales
#pragma unroll
        for (int mt = 0; mt < 2; mt++) {
            facc[mt][0][0] += (float)ci[mt][0][0] * s2a.x;
            facc[mt][0][1] += (float)ci[mt][0][1] * s2a.y;
            facc[mt][0][2] += (float)ci[mt][0][2] * s2a.x;
            facc[mt][0][3] += (float)ci[mt][0][3] * s2a.y;
            facc[mt][1][0] += (float)ci[mt][1][0] * s2b.x;
            facc[mt][1][1] += (float)ci[mt][1][1] * s2b.y;
            facc[mt][1][2] += (float)ci[mt][1][2] * s2b.x;
            facc[mt][1][3] += (float)ci[mt][1][3] * s2b.y;
        }
    }

    // ---------------- epilogue: * xs[row] + bias[col]; streaming stores ----------------
#pragma unroll
    for (int mt = 0; mt < 2; mt++) {
        const int r0 = m0 + wm * 32 + mt * 16 + (lane >> 2);
        const float xs0 = g_xs[r0];
        const float xs1 = g_xs[r0 + 8];
#pragma unroll
        for (int nt = 0; nt < 2; nt++) {
            const int col = n0 + wn * 16 + nt * 8 + (lane & 3) * 2;
            const float2 b2 = __ldg(reinterpret_cast<const float2*>(bias + col));
            float2 o0, o1;
            o0.x = facc[mt][nt][0] * xs0 + b2.x;
            o0.y = facc[mt][nt][1] * xs0 + b2.y;
            o1.x = facc[mt][nt][2] * xs1 + b2.x;
            o1.y = facc[mt][nt][3] * xs1 + b2.y;
            stg_cs_f2(out + (size_t)r0 * NDIM + col, o0);
            stg_cs_f2(out + (size_t)(r0 + 8) * NDIM + col, o1);
        }
    }
}

// ---------------- launch: inputs identified BY SIZE (order-proof) ----------------
extern "C" void kernel_launch(void* const* d_in, const int* in_sizes, int n_in,
                              void* d_out, int out_size) {
    const float* x = nullptr;          // 33554432 elems (float32)
    const int* wq32 = nullptr;         // 16777216 elems (int8 sign-extended to int32)
    const float* ws = nullptr;         // 131072 elems (float32)
    const float* bias = nullptr;       // 4096 elems (float32)
    for (int i = 0; i < n_in; i++) {
        long long sz = in_sizes[i];
        if (sz == (long long)MDIM * KDIM)      x = (const float*)d_in[i];
        else if (sz == (long long)NDIM * KDIM) wq32 = (const int*)d_in[i];
        else if (sz == (long long)NBLK * NDIM) ws = (const float*)d_in[i];
        else if (sz == NDIM)                   bias = (const float*)d_in[i];
    }
    float* out = (float*)d_out;

    cudaFuncSetAttribute(gemm_kernel, cudaFuncAttributeMaxDynamicSharedMemorySize, SMEM_DYN);

    prep_kernel<<<MDIM + NDIM, 256>>>(x, wq32);
    gemm_kernel<<<dim3(NDIM / 64, MDIM / 64, 1), 256, SMEM_DYN>>>(ws, bias, out);
}

// round 16
// speedup vs baseline: 1.0558x; 1.0558x over previous
#include <cuda_runtime.h>
#include <cuda_fp16.h>
#include <cuda_bf16.h>
#include <cstdint>
#include <cstddef>

#define MDIM 8192
#define KDIM 4096
#define NDIM 4096
#define NBLK 32            // K blocks of 128 for weight scales

// ---------------- static device scratch ----------------
__device__ __align__(1024) signed char g_xq[(size_t)MDIM * KDIM];  // int8 activations
__device__ __align__(1024) signed char g_wq[(size_t)NDIM * KDIM];  // int8 weights (packed from int32 input)
__device__ float g_xs[MDIM];                                        // per-row activation scales

// ---------------- helpers ----------------
__device__ __forceinline__ uint32_t smem_u32(const void* p) {
    uint32_t a;
    asm("{ .reg .u64 t; cvta.to.shared.u64 t, %1; cvt.u32.u64 %0, t; }" : "=r"(a) : "l"(p));
    return a;
}
__device__ __forceinline__ void cp_async16(uint32_t dst_smem, const void* src) {
    asm volatile("cp.async.cg.shared.global [%0], [%1], 16;" :: "r"(dst_smem), "l"(src) : "memory");
}
__device__ __forceinline__ void cp_commit() {
    asm volatile("cp.async.commit_group;" ::: "memory");
}
__device__ __forceinline__ void ldsm_x4(uint32_t* r, uint32_t addr) {
    asm volatile("ldmatrix.sync.aligned.m8n8.x4.shared.b16 {%0,%1,%2,%3}, [%4];"
        : "=r"(r[0]), "=r"(r[1]), "=r"(r[2]), "=r"(r[3]) : "r"(addr));
}
__device__ __forceinline__ void imma16832(int* d, const uint32_t* a, uint32_t b0, uint32_t b1) {
    asm volatile("mma.sync.aligned.m16n8k32.row.col.s32.s8.s8.s32 "
        "{%0,%1,%2,%3}, {%4,%5,%6,%7}, {%8,%9}, {%0,%1,%2,%3};"
        : "+r"(d[0]), "+r"(d[1]), "+r"(d[2]), "+r"(d[3])
        : "r"(a[0]), "r"(a[1]), "r"(a[2]), "r"(a[3]), "r"(b0), "r"(b1));
}
__device__ __forceinline__ void stg_cs_f2(float* p, float2 v) {
    asm volatile("st.global.cs.v2.f32 [%0], {%1, %2};" :: "l"(p), "f"(v.x), "f"(v.y) : "memory");
}
__device__ __forceinline__ uint32_t pack4b(int a, int b, int c, int d) {
    return (uint32_t)(a & 0xFF) | ((uint32_t)(b & 0xFF) << 8) |
           ((uint32_t)(c & 0xFF) << 16) | ((uint32_t)(d & 0xFF) << 24);
}

// ---------------- kernel 1: fused prep (quant x rows | pack weight rows), 16B stores ----------------
__global__ void __launch_bounds__(256) prep_kernel(const float* __restrict__ x,
                                                   const int* __restrict__ wq32) {
    const int t = threadIdx.x;
    if (blockIdx.x >= MDIM) {
        // pack one weight row: 4 consecutive int4 in -> one int4 (16 bytes) out
        const int r = blockIdx.x - MDIM;
        const int4* src = reinterpret_cast<const int4*>(wq32 + (size_t)r * KDIM);
        uint4* dst = reinterpret_cast<uint4*>(g_wq + (size_t)r * KDIM);
        int4 v[4];
#pragma unroll
        for (int j = 0; j < 4; j++) v[j] = src[4 * t + j];
        uint4 o;
        o.x = pack4b(v[0].x, v[0].y, v[0].z, v[0].w);
        o.y = pack4b(v[1].x, v[1].y, v[1].z, v[1].w);
        o.z = pack4b(v[2].x, v[2].y, v[2].z, v[2].w);
        o.w = pack4b(v[3].x, v[3].y, v[3].z, v[3].w);
        dst[t] = o;
        return;
    }
    // quantize one activation row: 4 consecutive float4 in -> one int4 out
    const int row = blockIdx.x;
    const float4* xr = reinterpret_cast<const float4*>(x) + (size_t)row * (KDIM / 4);
    float4 v[4];
    float amax = 0.f;
#pragma unroll
    for (int j = 0; j < 4; j++) {
        v[j] = xr[4 * t + j];
        amax = fmaxf(amax, fmaxf(fmaxf(fabsf(v[j].x), fabsf(v[j].y)), fmaxf(fabsf(v[j].z), fabsf(v[j].w))));
    }
#pragma unroll
    for (int o = 16; o; o >>= 1) amax = fmaxf(amax, __shfl_xor_sync(0xffffffffu, amax, o));
    __shared__ float warpmax[8];
    __shared__ float s_scale;
    if ((t & 31) == 0) warpmax[t >> 5] = amax;
    __syncthreads();
    if (t == 0) {
        float m = warpmax[0];
#pragma unroll
        for (int i = 1; i < 8; i++) m = fmaxf(m, warpmax[i]);
        float s = fmaxf(m, 1e-6f) / 127.0f;
        g_xs[row] = s;
        s_scale = s;
    }
    __syncthreads();
    const float s = s_scale;
    uint4 o;
    uint32_t* op = &o.x;
#pragma unroll
    for (int j = 0; j < 4; j++) {
        int qa = max(-128, min(127, __float2int_rn(v[j].x / s)));
        int qb = max(-128, min(127, __float2int_rn(v[j].y / s)));
        int qc = max(-128, min(127, __float2int_rn(v[j].z / s)));
        int qd = max(-128, min(127, __float2int_rn(v[j].w / s)));
        op[j] = pack4b(qa, qb, qc, qd);
    }
    reinterpret_cast<uint4*>(g_xq + (size_t)row * KDIM)[t] = o;
}

// ---------------- kernel 2: int8 GEMM, CTA 64(M)x64(N), 256 thr, 3 CTAs/SM ----------------
// (R14-exact mainloop: scales loaded in the fixup, AFTER the MMA chain)
// 8 warps: wm = wid&1 (M offset 32*wm), wn = wid>>1 (N offset 16*wn). Warp tile 32x16.
// One B ldmatrix.x4 per k32 step covers n16 x k32 (frags 0,1 = rows0-7; 2,3 = rows8-15).
// SMEM rows padded to 144B for conflict-free ldmatrix.

#define ROWB 144
#define TILE_A_BYTES (64 * ROWB)           // 9216
#define TILE_B_BYTES (64 * ROWB)           // 9216
#define STAGE_BYTES (TILE_A_BYTES + TILE_B_BYTES)   // 18432
#define STAGES 4
#define SMEM_DYN (STAGES * STAGE_BYTES)    // 73728 -> 3 CTAs/SM (216KB)

__device__ __forceinline__ void load_stage(uint32_t sbase, const signed char* gA,
                                           const signed char* gB, int blk, int tid) {
    const int koff = blk * 128;
#pragma unroll
    for (int i = 0; i < 2; i++) {            // A: 512 x 16B chunks, 256 threads
        int idx = tid + i * 256;
        int r = idx >> 3, c = idx & 7;
        cp_async16(sbase + (uint32_t)r * ROWB + (uint32_t)(c << 4),
                   gA + (size_t)r * KDIM + koff + c * 16);
    }
    uint32_t bb = sbase + TILE_A_BYTES;
#pragma unroll
    for (int i = 0; i < 2; i++) {            // B: 512 x 16B chunks
        int idx = tid + i * 256;
        int r = idx >> 3, c = idx & 7;
        cp_async16(bb + (uint32_t)r * ROWB + (uint32_t)(c << 4),
                   gB + (size_t)r * KDIM + koff + c * 16);
    }
}

__global__ void __launch_bounds__(256, 3) gemm_kernel(const float* __restrict__ ws,
                                                      const float* __restrict__ bias,
                                                      float* __restrict__ out) {
    extern __shared__ char dsm[];

    const int tid = threadIdx.x;
    const int wid = tid >> 5;
    const int lane = tid & 31;
    const int wm = wid & 1;                  // M offset 32*wm
    const int wn = wid >> 1;                 // N offset 16*wn (0..3)
    const int m0 = blockIdx.y * 64;
    const int n0 = blockIdx.x * 64;
    const uint32_t sbase0 = smem_u32(dsm);

    const signed char* gA = g_xq + (size_t)m0 * KDIM;
    const signed char* gB = g_wq + (size_t)n0 * KDIM;

    float facc[2][2][4];
#pragma unroll
    for (int mt = 0; mt < 2; mt++)
#pragma unroll
        for (int nt = 0; nt < 2; nt++)
#pragma unroll
            for (int r = 0; r < 4; r++) facc[mt][nt][r] = 0.f;

    // prologue: fill 3 stages
#pragma unroll
    for (int s = 0; s < 3; s++) {
        load_stage(sbase0 + s * STAGE_BYTES, gA, gB, s, tid);
        cp_commit();
    }

    // ldmatrix base offsets (within a stage)
    const uint32_t a_lrow = (uint32_t)(wm * 32 + (lane & 15)) * ROWB + (uint32_t)(lane & 16);
    const uint32_t b_lrow = (uint32_t)(wn * 16 + (lane & 7) + ((lane & 16) >> 1)) * ROWB
                          + (uint32_t)((lane & 8) << 1);

    // per-thread weight-scale pointer: ws[blk*NDIM + col], col = n0 + wn*16 + nt*8 + (lane&3)*2
    const float* wsp = ws + n0 + wn * 16 + (lane & 3) * 2;

    for (int blk = 0; blk < NBLK; blk++) {
        asm volatile("cp.async.wait_group 2;" ::: "memory");
        __syncthreads();   // stage blk visible; all warps done with stage blk-1

        if (blk + 3 < NBLK)
            load_stage(sbase0 + ((blk + 3) & 3) * STAGE_BYTES, gA, gB, blk + 3, tid);
        cp_commit();

        const uint32_t abase = sbase0 + (blk & 3) * STAGE_BYTES;
        const uint32_t bbase = abase + TILE_A_BYTES;

        int ci[2][2][4];
#pragma unroll
        for (int mt = 0; mt < 2; mt++)
#pragma unroll
            for (int nt = 0; nt < 2; nt++)
#pragma unroll
                for (int r = 0; r < 4; r++) ci[mt][nt][r] = 0;

#pragma unroll
        for (int ks = 0; ks < 4; ks++) {
            const uint32_t kb = ks * 32;
            uint32_t af[2][4];
#pragma unroll
            for (int mt = 0; mt < 2; mt++)
                ldsm_x4(af[mt], abase + a_lrow + (uint32_t)(mt * 16) * ROWB + kb);
            uint32_t bf[4];
            ldsm_x4(bf, bbase + b_lrow + kb);
#pragma unroll
            for (int mt = 0; mt < 2; mt++)
#pragma unroll
                for (int nt = 0; nt < 2; nt++)
                    imma16832(ci[mt][nt], af[mt], bf[nt * 2], bf[nt * 2 + 1]);
        }

        // per-block fp32 fixup; scales straight from L2 (hot line, shared across CTAs)
        const float* wsb = wsp + (size_t)blk * NDIM;
#pragma unroll
        for (int nt = 0; nt < 2; nt++) {
            const float2 s2 = __ldg(reinterpret_cast<const float2*>(wsb + nt * 8));
#pragma unroll
            for (int mt = 0; mt < 2; mt++) {
                facc[mt][nt][0] += (float)ci[mt][nt][0] * s2.x;
                facc[mt][nt][1] += (float)ci[mt][nt][1] * s2.y;
                facc[mt][nt][2] += (float)ci[mt][nt][2] * s2.x;
                facc[mt][nt][3] += (float)ci[mt][nt][3] * s2.y;
            }
        }
    }

    // ---------------- epilogue: * xs[row] + bias[col]; streaming stores ----------------
#pragma unroll
    for (int mt = 0; mt < 2; mt++) {
        const int r0 = m0 + wm * 32 + mt * 16 + (lane >> 2);
        const float xs0 = g_xs[r0];
        const float xs1 = g_xs[r0 + 8];
#pragma unroll
        for (int nt = 0; nt < 2; nt++) {
            const int col = n0 + wn * 16 + nt * 8 + (lane & 3) * 2;
            const float2 b2 = __ldg(reinterpret_cast<const float2*>(bias + col));
            float2 o0, o1;
            o0.x = facc[mt][nt][0] * xs0 + b2.x;
            o0.y = facc[mt][nt][1] * xs0 + b2.y;
            o1.x = facc[mt][nt][2] * xs1 + b2.x;
            o1.y = facc[mt][nt][3] * xs1 + b2.y;
            stg_cs_f2(out + (size_t)r0 * NDIM + col, o0);
            stg_cs_f2(out + (size_t)(r0 + 8) * NDIM + col, o1);
        }
    }
}

// ---------------- launch: inputs identified BY SIZE (order-proof) ----------------
extern "C" void kernel_launch(void* const* d_in, const int* in_sizes, int n_in,
                              void* d_out, int out_size) {
    const float* x = nullptr;          // 33554432 elems (float32)
    const int* wq32 = nullptr;         // 16777216 elems (int8 sign-extended to int32)
    const float* ws = nullptr;         // 131072 elems (float32)
    const float* bias = nullptr;       // 4096 elems (float32)
    for (int i = 0; i < n_in; i++) {
        long long sz = in_sizes[i];
        if (sz == (long long)MDIM * KDIM)      x = (const float*)d_in[i];
        else if (sz == (long long)NDIM * KDIM) wq32 = (const int*)d_in[i];
        else if (sz == (long long)NBLK * NDIM) ws = (const float*)d_in[i];
        else if (sz == NDIM)                   bias = (const float*)d_in[i];
    }
    float* out = (float*)d_out;

    cudaFuncSetAttribute(gemm_kernel, cudaFuncAttributeMaxDynamicSharedMemorySize, SMEM_DYN);

    prep_kernel<<<MDIM + NDIM, 256>>>(x, wq32);
    gemm_kernel<<<dim3(NDIM / 64, MDIM / 64, 1), 256, SMEM_DYN>>>(ws, bias, out);
}

// round 17
// speedup vs baseline: 1.0577x; 1.0018x over previous
#include <cuda_runtime.h>
#include <cuda_fp16.h>
#include <cuda_bf16.h>
#include <cstdint>
#include <cstddef>

#define MDIM 8192
#define KDIM 4096
#define NDIM 4096
#define NBLK 32            // K blocks of 128 for weight scales

// ---------------- static device scratch ----------------
__device__ __align__(1024) signed char g_xq[(size_t)MDIM * KDIM];  // int8 activations
__device__ __align__(1024) signed char g_wq[(size_t)NDIM * KDIM];  // int8 weights (packed from int32 input)
__device__ float g_xs[MDIM];                                        // per-row activation scales

// ---------------- helpers ----------------
__device__ __forceinline__ uint32_t smem_u32(const void* p) {
    uint32_t a;
    asm("{ .reg .u64 t; cvta.to.shared.u64 t, %1; cvt.u32.u64 %0, t; }" : "=r"(a) : "l"(p));
    return a;
}
__device__ __forceinline__ void cp_async16(uint32_t dst_smem, const void* src) {
    asm volatile("cp.async.cg.shared.global [%0], [%1], 16;" :: "r"(dst_smem), "l"(src) : "memory");
}
__device__ __forceinline__ void cp_commit() {
    asm volatile("cp.async.commit_group;" ::: "memory");
}
__device__ __forceinline__ void ldsm_x4(uint32_t* r, uint32_t addr) {
    asm volatile("ldmatrix.sync.aligned.m8n8.x4.shared.b16 {%0,%1,%2,%3}, [%4];"
        : "=r"(r[0]), "=r"(r[1]), "=r"(r[2]), "=r"(r[3]) : "r"(addr));
}
__device__ __forceinline__ void imma16832(int* d, const uint32_t* a, uint32_t b0, uint32_t b1) {
    asm volatile("mma.sync.aligned.m16n8k32.row.col.s32.s8.s8.s32 "
        "{%0,%1,%2,%3}, {%4,%5,%6,%7}, {%8,%9}, {%0,%1,%2,%3};"
        : "+r"(d[0]), "+r"(d[1]), "+r"(d[2]), "+r"(d[3])
        : "r"(a[0]), "r"(a[1]), "r"(a[2]), "r"(a[3]), "r"(b0), "r"(b1));
}
__device__ __forceinline__ void stg_cs_f2(float* p, float2 v) {
    asm volatile("st.global.cs.v2.f32 [%0], {%1, %2};" :: "l"(p), "f"(v.x), "f"(v.y) : "memory");
}
__device__ __forceinline__ uint32_t pack4b(int a, int b, int c, int d) {
    return (uint32_t)(a & 0xFF) | ((uint32_t)(b & 0xFF) << 8) |
           ((uint32_t)(c & 0xFF) << 16) | ((uint32_t)(d & 0xFF) << 24);
}

// ---------------- kernel 1: fused prep (quant x rows | pack weight rows), 16B stores ----------------
__global__ void __launch_bounds__(256) prep_kernel(const float* __restrict__ x,
                                                   const int* __restrict__ wq32) {
    const int t = threadIdx.x;
    if (blockIdx.x >= MDIM) {
        // pack one weight row: 4 consecutive int4 in -> one int4 (16 bytes) out
        const int r = blockIdx.x - MDIM;
        const int4* src = reinterpret_cast<const int4*>(wq32 + (size_t)r * KDIM);
        uint4* dst = reinterpret_cast<uint4*>(g_wq + (size_t)r * KDIM);
        int4 v[4];
#pragma unroll
        for (int j = 0; j < 4; j++) v[j] = src[4 * t + j];
        uint4 o;
        o.x = pack4b(v[0].x, v[0].y, v[0].z, v[0].w);
        o.y = pack4b(v[1].x, v[1].y, v[1].z, v[1].w);
        o.z = pack4b(v[2].x, v[2].y, v[2].z, v[2].w);
        o.w = pack4b(v[3].x, v[3].y, v[3].z, v[3].w);
        dst[t] = o;
        return;
    }
    // quantize one activation row: 4 consecutive float4 in -> one int4 out
    const int row = blockIdx.x;
    const float4* xr = reinterpret_cast<const float4*>(x) + (size_t)row * (KDIM / 4);
    float4 v[4];
    float amax = 0.f;
#pragma unroll
    for (int j = 0; j < 4; j++) {
        v[j] = xr[4 * t + j];
        amax = fmaxf(amax, fmaxf(fmaxf(fabsf(v[j].x), fabsf(v[j].y)), fmaxf(fabsf(v[j].z), fabsf(v[j].w))));
    }
#pragma unroll
    for (int o = 16; o; o >>= 1) amax = fmaxf(amax, __shfl_xor_sync(0xffffffffu, amax, o));
    __shared__ float warpmax[8];
    __shared__ float s_scale;
    if ((t & 31) == 0) warpmax[t >> 5] = amax;
    __syncthreads();
    if (t == 0) {
        float m = warpmax[0];
#pragma unroll
        for (int i = 1; i < 8; i++) m = fmaxf(m, warpmax[i]);
        float s = fmaxf(m, 1e-6f) / 127.0f;
        g_xs[row] = s;
        s_scale = s;
    }
    __syncthreads();
    const float s = s_scale;
    uint4 o;
    uint32_t* op = &o.x;
#pragma unroll
    for (int j = 0; j < 4; j++) {
        int qa = max(-128, min(127, __float2int_rn(v[j].x / s)));
        int qb = max(-128, min(127, __float2int_rn(v[j].y / s)));
        int qc = max(-128, min(127, __float2int_rn(v[j].z / s)));
        int qd = max(-128, min(127, __float2int_rn(v[j].w / s)));
        op[j] = pack4b(qa, qb, qc, qd);
    }
    reinterpret_cast<uint4*>(g_xq + (size_t)row * KDIM)[t] = o;
}

// ---------------- kernel 2: int8 GEMM, CTA 64(M)x64(N), 256 thr, 3-stage pipe, 4 CTAs/SM ----------------
// 8 warps: wm = wid&1 (M offset 32*wm), wn = wid>>1 (N offset 16*wn). Warp tile 32x16.
// One B ldmatrix.x4 per k32 step covers n16 x k32 (frags 0,1 = rows0-7; 2,3 = rows8-15).
// SMEM rows padded to 144B for conflict-free ldmatrix. 3 stages (55.3KB) -> 4 CTAs/SM.
// Pipeline: prologue commits fills 0,1; iter blk: wait_group 1 (=> fill blk done), sync,
// fill stage (blk+2)%3 (stage blk-1, freed by this barrier), commit.

#define ROWB 144
#define TILE_A_BYTES (64 * ROWB)           // 9216
#define TILE_B_BYTES (64 * ROWB)           // 9216
#define STAGE_BYTES (TILE_A_BYTES + TILE_B_BYTES)   // 18432
#define STAGES 3
#define SMEM_DYN (STAGES * STAGE_BYTES)    // 55296 -> 4 CTAs/SM (221KB)

__device__ __forceinline__ uint32_t stage_off(int blk) {
    // (blk % 3) * STAGE_BYTES without divide: blk mod 3 via lookup-free loop-carried is
    // messy; use fast mod: blk - (blk/3)*3 (compiler strength-reduces to mul-shift).
    return (uint32_t)(blk % 3) * STAGE_BYTES;
}

__device__ __forceinline__ void load_stage(uint32_t sbase, const signed char* gA,
                                           const signed char* gB, int blk, int tid) {
    const int koff = blk * 128;
#pragma unroll
    for (int i = 0; i < 2; i++) {            // A: 512 x 16B chunks, 256 threads
        int idx = tid + i * 256;
        int r = idx >> 3, c = idx & 7;
        cp_async16(sbase + (uint32_t)r * ROWB + (uint32_t)(c << 4),
                   gA + (size_t)r * KDIM + koff + c * 16);
    }
    uint32_t bb = sbase + TILE_A_BYTES;
#pragma unroll
    for (int i = 0; i < 2; i++) {            // B: 512 x 16B chunks
        int idx = tid + i * 256;
        int r = idx >> 3, c = idx & 7;
        cp_async16(bb + (uint32_t)r * ROWB + (uint32_t)(c << 4),
                   gB + (size_t)r * KDIM + koff + c * 16);
    }
}

__global__ void __launch_bounds__(256, 4) gemm_kernel(const float* __restrict__ ws,
                                                      const float* __restrict__ bias,
                                                      float* __restrict__ out) {
    extern __shared__ char dsm[];

    const int tid = threadIdx.x;
    const int wid = tid >> 5;
    const int lane = tid & 31;
    const int wm = wid & 1;                  // M offset 32*wm
    const int wn = wid >> 1;                 // N offset 16*wn (0..3)
    const int m0 = blockIdx.y * 64;
    const int n0 = blockIdx.x * 64;
    const uint32_t sbase0 = smem_u32(dsm);

    const signed char* gA = g_xq + (size_t)m0 * KDIM;
    const signed char* gB = g_wq + (size_t)n0 * KDIM;

    float facc[2][2][4];
#pragma unroll
    for (int mt = 0; mt < 2; mt++)
#pragma unroll
        for (int nt = 0; nt < 2; nt++)
#pragma unroll
            for (int r = 0; r < 4; r++) facc[mt][nt][r] = 0.f;

    // prologue: fill 2 stages
#pragma unroll
    for (int s = 0; s < 2; s++) {
        load_stage(sbase0 + s * STAGE_BYTES, gA, gB, s, tid);
        cp_commit();
    }

    // ldmatrix base offsets (within a stage)
    const uint32_t a_lrow = (uint32_t)(wm * 32 + (lane & 15)) * ROWB + (uint32_t)(lane & 16);
    const uint32_t b_lrow = (uint32_t)(wn * 16 + (lane & 7) + ((lane & 16) >> 1)) * ROWB
                          + (uint32_t)((lane & 8) << 1);

    // per-thread weight-scale pointer: ws[blk*NDIM + col], col = n0 + wn*16 + nt*8 + (lane&3)*2
    const float* wsp = ws + n0 + wn * 16 + (lane & 3) * 2;

    for (int blk = 0; blk < NBLK; blk++) {
        asm volatile("cp.async.wait_group 1;" ::: "memory");
        __syncthreads();   // stage blk visible; all warps done with stage blk-1

        if (blk + 2 < NBLK)
            load_stage(sbase0 + stage_off(blk + 2), gA, gB, blk + 2, tid);
        cp_commit();

        const uint32_t abase = sbase0 + stage_off(blk);
        const uint32_t bbase = abase + TILE_A_BYTES;

        int ci[2][2][4];
#pragma unroll
        for (int mt = 0; mt < 2; mt++)
#pragma unroll
            for (int nt = 0; nt < 2; nt++)
#pragma unroll
                for (int r = 0; r < 4; r++) ci[mt][nt][r] = 0;

#pragma unroll
        for (int ks = 0; ks < 4; ks++) {
            const uint32_t kb = ks * 32;
            uint32_t af[2][4];
#pragma unroll
            for (int mt = 0; mt < 2; mt++)
                ldsm_x4(af[mt], abase + a_lrow + (uint32_t)(mt * 16) * ROWB + kb);
            uint32_t bf[4];
            ldsm_x4(bf, bbase + b_lrow + kb);
#pragma unroll
            for (int mt = 0; mt < 2; mt++)
#pragma unroll
                for (int nt = 0; nt < 2; nt++)
                    imma16832(ci[mt][nt], af[mt], bf[nt * 2], bf[nt * 2 + 1]);
        }

        // per-block fp32 fixup; scales straight from L2 (hot line, shared across CTAs)
        const float* wsb = wsp + (size_t)blk * NDIM;
#pragma unroll
        for (int nt = 0; nt < 2; nt++) {
            const float2 s2 = __ldg(reinterpret_cast<const float2*>(wsb + nt * 8));
#pragma unroll
            for (int mt = 0; mt < 2; mt++) {
                facc[mt][nt][0] += (float)ci[mt][nt][0] * s2.x;
                facc[mt][nt][1] += (float)ci[mt][nt][1] * s2.y;
                facc[mt][nt][2] += (float)ci[mt][nt][2] * s2.x;
                facc[mt][nt][3] += (float)ci[mt][nt][3] * s2.y;
            }
        }
    }

    // ---------------- epilogue: * xs[row] + bias[col]; streaming stores ----------------
#pragma unroll
    for (int mt = 0; mt < 2; mt++) {
        const int r0 = m0 + wm * 32 + mt * 16 + (lane >> 2);
        const float xs0 = g_xs[r0];
        const float xs1 = g_xs[r0 + 8];
#pragma unroll
        for (int nt = 0; nt < 2; nt++) {
            const int col = n0 + wn * 16 + nt * 8 + (lane & 3) * 2;
            const float2 b2 = __ldg(reinterpret_cast<const float2*>(bias + col));
            float2 o0, o1;
            o0.x = facc[mt][nt][0] * xs0 + b2.x;
            o0.y = facc[mt][nt][1] * xs0 + b2.y;
            o1.x = facc[mt][nt][2] * xs1 + b2.x;
            o1.y = facc[mt][nt][3] * xs1 + b2.y;
            stg_cs_f2(out + (size_t)r0 * NDIM + col, o0);
            stg_cs_f2(out + (size_t)(r0 + 8) * NDIM + col, o1);
        }
    }
}

// ---------------- launch: inputs identified BY SIZE (order-proof) ----------------
extern "C" void kernel_launch(void* const* d_in, const int* in_sizes, int n_in,
                              void* d_out, int out_size) {
    const float* x = nullptr;          // 33554432 elems (float32)
    const int* wq32 = nullptr;         // 16777216 elems (int8 sign-extended to int32)
    const float* ws = nullptr;         // 131072 elems (float32)
    const float* bias = nullptr;       // 4096 elems (float32)
    for (int i = 0; i < n_in; i++) {
        long long sz = in_sizes[i];
        if (sz == (long long)MDIM * KDIM)      x = (const float*)d_in[i];
        else if (sz == (long long)NDIM * KDIM) wq32 = (const int*)d_in[i];
        else if (sz == (long long)NBLK * NDIM) ws = (const float*)d_in[i];
        else if (sz == NDIM)                   bias = (const float*)d_in[i];
    }
    float* out = (float*)d_out;

    cudaFuncSetAttribute(gemm_kernel, cudaFuncAttributeMaxDynamicSharedMemorySize, SMEM_DYN);

    prep_kernel<<<MDIM + NDIM, 256>>>(x, wq32);
    gemm_kernel<<<dim3(NDIM / 64, MDIM / 64, 1), 256, SMEM_DYN>>>(ws, bias, out);
}